// round 2
// baseline (speedup 1.0000x reference)
#include <cuda_runtime.h>

#define NHID 1024
#define NTPC 225
#define NCLS 224
#define BATCH 2048
#define SB 8           // samples per block chunk
#define SLSTRIDE 232   // padded logits row stride in smem

// ---------------- scratch (device globals; no allocs allowed) ----------------
__device__ int   g_count[NCLS];
__device__ int   g_fill[NCLS];
__device__ int   g_offset[NCLS + 1];
__device__ int   g_order[BATCH];
__device__ int   g_class[BATCH];
__device__ int   g_tok[BATCH];
__device__ float g_topprob[BATCH];

// ---------------- tiny setup kernels ----------------
__global__ void k_zero() {
    int t = threadIdx.x;
    if (t < NCLS) { g_count[t] = 0; g_fill[t] = 0; }
}

__global__ void k_count(const int* __restrict__ labels) {
    int i = blockIdx.x * blockDim.x + threadIdx.x;
    if (i < BATCH) {
        int l = labels[i];
        int c = l / NTPC;
        c = min(max(c, 0), NCLS - 1);          // defensive clamp
        g_class[i] = c;
        g_tok[i]   = l - c * NTPC;
        atomicAdd(&g_count[c], 1);
    }
}

__global__ void k_scan() {
    if (threadIdx.x == 0) {
        int acc = 0;
        for (int c = 0; c < NCLS; c++) { g_offset[c] = acc; acc += g_count[c]; }
        g_offset[NCLS] = acc;
    }
}

__global__ void k_scatter() {
    int i = blockIdx.x * blockDim.x + threadIdx.x;
    if (i < BATCH) {
        int c = g_class[i];
        int pos = g_offset[c] + atomicAdd(&g_fill[c], 1);
        g_order[pos] = i;
    }
}

// ---------------- top: GEMM [8,1024]x[1024,224] + softmax + select ----------------
// grid = BATCH/SB blocks, 256 threads. thread t (<224) owns class-column t.
__global__ __launch_bounds__(256) void k_top(const float* __restrict__ x,
                                             const float* __restrict__ W,
                                             const float* __restrict__ b) {
    __shared__ float sx[NHID * SB];        // [k][u]
    __shared__ float sl[SB * SLSTRIDE];    // logits per sample
    int tid  = threadIdx.x;
    int base = blockIdx.x * SB;

    // stage 8 input rows into smem, transposed to [k][u]
    for (int idx = tid; idx < (NHID / 4) * SB; idx += blockDim.x) {
        int u  = idx / (NHID / 4);
        int k4 = (idx % (NHID / 4)) * 4;
        float4 v = *(const float4*)&x[(size_t)(base + u) * NHID + k4];
        sx[(k4 + 0) * SB + u] = v.x;
        sx[(k4 + 1) * SB + u] = v.y;
        sx[(k4 + 2) * SB + u] = v.z;
        sx[(k4 + 3) * SB + u] = v.w;
    }
    __syncthreads();

    if (tid < NCLS) {
        float acc[SB];
        float bb = b[tid];
        #pragma unroll
        for (int u = 0; u < SB; u++) acc[u] = bb;
        #pragma unroll 4
        for (int k = 0; k < NHID; k++) {
            float w = __ldg(&W[k * NCLS + tid]);
            #pragma unroll
            for (int u = 0; u < SB; u++) acc[u] += sx[k * SB + u] * w;
        }
        #pragma unroll
        for (int u = 0; u < SB; u++) sl[u * SLSTRIDE + tid] = acc[u];
    }
    __syncthreads();

    // warp u reduces sample u's 224 logits
    int wid = tid >> 5, lane = tid & 31;
    if (wid < SB) {
        int i = base + wid;
        float v[7];
        #pragma unroll
        for (int j = 0; j < 7; j++) v[j] = sl[wid * SLSTRIDE + lane + j * 32];
        float m = v[0];
        #pragma unroll
        for (int j = 1; j < 7; j++) m = fmaxf(m, v[j]);
        #pragma unroll
        for (int o = 16; o > 0; o >>= 1) m = fmaxf(m, __shfl_xor_sync(0xffffffffu, m, o));
        float s = 0.f;
        #pragma unroll
        for (int j = 0; j < 7; j++) s += __expf(v[j] - m);
        #pragma unroll
        for (int o = 16; o > 0; o >>= 1) s += __shfl_xor_sync(0xffffffffu, s, o);
        if (lane == 0) {
            int c = g_class[i];
            g_topprob[i] = __expf(sl[wid * SLSTRIDE + c] - m) / s;
        }
    }
}

// ---------------- bottom: grouped-by-class GEMM + softmax + combine ----------------
// grid = (224, 4). block (c, y) handles sample chunks y, y+4, ... of class c.
__global__ __launch_bounds__(256) void k_bottom(const float* __restrict__ x,
                                                const float* __restrict__ W,
                                                const float* __restrict__ b,
                                                float* __restrict__ out) {
    __shared__ float sx[NHID * SB];
    __shared__ float sl[SB * SLSTRIDE];
    __shared__ int   sid[SB];

    int c   = blockIdx.x;
    int n   = g_count[c];
    int off = g_offset[c];
    int tid = threadIdx.x;
    const float* Wc = W + (size_t)c * NHID * NTPC;

    for (int chunk = blockIdx.y; chunk * SB < n; chunk += gridDim.y) {
        int nv = min(SB, n - chunk * SB);
        if (tid < SB) sid[tid] = (tid < nv) ? g_order[off + chunk * SB + tid] : -1;
        __syncthreads();

        for (int idx = tid; idx < (NHID / 4) * SB; idx += blockDim.x) {
            int u  = idx / (NHID / 4);
            int k4 = (idx % (NHID / 4)) * 4;
            float4 v = (u < nv) ? *(const float4*)&x[(size_t)sid[u] * NHID + k4]
                                : make_float4(0.f, 0.f, 0.f, 0.f);
            sx[(k4 + 0) * SB + u] = v.x;
            sx[(k4 + 1) * SB + u] = v.y;
            sx[(k4 + 2) * SB + u] = v.z;
            sx[(k4 + 3) * SB + u] = v.w;
        }
        __syncthreads();

        if (tid < NTPC) {
            float acc[SB];
            float bb = b[c * NTPC + tid];
            #pragma unroll
            for (int u = 0; u < SB; u++) acc[u] = bb;
            #pragma unroll 4
            for (int k = 0; k < NHID; k++) {
                float w = __ldg(&Wc[k * NTPC + tid]);
                #pragma unroll
                for (int u = 0; u < SB; u++) acc[u] += sx[k * SB + u] * w;
            }
            #pragma unroll
            for (int u = 0; u < SB; u++) sl[u * SLSTRIDE + tid] = acc[u];
        }
        __syncthreads();

        int wid = tid >> 5, lane = tid & 31;
        if (wid < nv) {
            int i = sid[wid];
            float v[8];
            #pragma unroll
            for (int j = 0; j < 8; j++) {
                int idx = lane + j * 32;
                v[j] = (idx < NTPC) ? sl[wid * SLSTRIDE + idx] : -1e30f;
            }
            float m = v[0];
            #pragma unroll
            for (int j = 1; j < 8; j++) m = fmaxf(m, v[j]);
            #pragma unroll
            for (int o = 16; o > 0; o >>= 1) m = fmaxf(m, __shfl_xor_sync(0xffffffffu, m, o));
            float s = 0.f;
            #pragma unroll
            for (int j = 0; j < 8; j++) {
                int idx = lane + j * 32;
                s += (idx < NTPC) ? __expf(v[j] - m) : 0.f;
            }
            #pragma unroll
            for (int o = 16; o > 0; o >>= 1) s += __shfl_xor_sync(0xffffffffu, s, o);
            if (lane == 0) {
                int tp = g_tok[i];
                float bprob = __expf(sl[wid * SLSTRIDE + tp] - m) / s;
                out[i] = g_topprob[i] * bprob;
            }
        }
        __syncthreads();
    }
}

// ---------------- launch ----------------
extern "C" void kernel_launch(void* const* d_in, const int* in_sizes, int n_in,
                              void* d_out, int out_size) {
    const float* inputs = (const float*)d_in[0];
    const int*   labels = (const int*)d_in[1];     // int32: JAX downcasts int64 without x64
    const float* topW   = (const float*)d_in[2];
    const float* topB   = (const float*)d_in[3];
    const float* botW   = (const float*)d_in[4];
    const float* botB   = (const float*)d_in[5];
    float*       out    = (float*)d_out;

    k_zero<<<1, 256>>>();
    k_count<<<(BATCH + 255) / 256, 256>>>(labels);
    k_scan<<<1, 32>>>();
    k_scatter<<<(BATCH + 255) / 256, 256>>>();
    k_top<<<BATCH / SB, 256>>>(inputs, topW, topB);
    k_bottom<<<dim3(NCLS, 4), 256>>>(inputs, botW, botB, out);
}

// round 3
// speedup vs baseline: 1.2316x; 1.2316x over previous
#include <cuda_runtime.h>

#define NHID 1024
#define NTPC 225
#define NCLS 224
#define BATCH 2048
#define SBT 16          // samples per tile
#define SLSTRIDE 232    // padded logits row stride (floats)
#define SMEM_BYTES (NHID * SBT * 4)   // 64 KB

// ---------------- scratch ----------------
__device__ int   g_count[NCLS];
__device__ int   g_offset[NCLS];
__device__ int   g_order[BATCH];
__device__ int   g_class[BATCH];
__device__ int   g_tok[BATCH];
__device__ float g_topprob[BATCH];

// ---------------- f32x2 helpers ----------------
__device__ __forceinline__ unsigned long long pack2(float a) {
    unsigned long long r;
    asm("mov.b64 %0, {%1, %1};" : "=l"(r) : "r"(__float_as_uint(a)));
    return r;
}
__device__ __forceinline__ void fma2(unsigned long long& a, unsigned long long x,
                                     unsigned long long w) {
    asm("fma.rn.f32x2 %0, %1, %2, %0;" : "+l"(a) : "l"(x), "l"(w));
}
__device__ __forceinline__ float lo2(unsigned long long a) { return __uint_as_float((unsigned)a); }
__device__ __forceinline__ float hi2(unsigned long long a) { return __uint_as_float((unsigned)(a >> 32)); }

// ---------------- fused preprocessing: count + scan + scatter ----------------
__global__ __launch_bounds__(256) void k_prep(const int* __restrict__ labels) {
    __shared__ int scount[NCLS];
    __shared__ int soff[NCLS];
    __shared__ int sfill[NCLS];
    int tid = threadIdx.x;
    if (tid < NCLS) { scount[tid] = 0; sfill[tid] = 0; }
    __syncthreads();

    for (int i = tid; i < BATCH; i += 256) {
        int l = labels[i];
        int c = l / NTPC;
        c = min(max(c, 0), NCLS - 1);
        g_class[i] = c;
        g_tok[i]   = l - c * NTPC;
        atomicAdd(&scount[c], 1);
    }
    __syncthreads();

    if (tid == 0) {
        int acc = 0;
        for (int c = 0; c < NCLS; c++) { soff[c] = acc; acc += scount[c]; }
    }
    __syncthreads();

    if (tid < NCLS) { g_count[tid] = scount[tid]; g_offset[tid] = soff[tid]; }

    for (int i = tid; i < BATCH; i += 256) {
        int c = g_class[i];
        int pos = soff[c] + atomicAdd(&sfill[c], 1);
        g_order[pos] = i;
    }
}

// ---------------- top: [16,1024]x[1024,224] + softmax + select ----------------
__global__ __launch_bounds__(256) void k_top(const float* __restrict__ x,
                                             const float* __restrict__ W,
                                             const float* __restrict__ b) {
    extern __shared__ float smem[];
    float* sx = smem;   // [k][16]
    float* sl = smem;   // overlay after GEMM
    int tid  = threadIdx.x;
    int base = blockIdx.x * SBT;

    for (int idx = tid; idx < (NHID / 4) * SBT; idx += 256) {
        int u  = idx / (NHID / 4);
        int k4 = (idx % (NHID / 4)) * 4;
        float4 v = *(const float4*)&x[(size_t)(base + u) * NHID + k4];
        sx[(k4 + 0) * SBT + u] = v.x;
        sx[(k4 + 1) * SBT + u] = v.y;
        sx[(k4 + 2) * SBT + u] = v.z;
        sx[(k4 + 3) * SBT + u] = v.w;
    }
    __syncthreads();

    unsigned long long acc[8];
    if (tid < NCLS) {
        unsigned long long bb = pack2(b[tid]);
        #pragma unroll
        for (int j = 0; j < 8; j++) acc[j] = bb;
        #pragma unroll 8
        for (int k = 0; k < NHID; k++) {
            unsigned long long wv = pack2(__ldg(&W[k * NCLS + tid]));
            const ulonglong2* xp = (const ulonglong2*)(sx + k * SBT);
            #pragma unroll
            for (int j = 0; j < 4; j++) {
                ulonglong2 p = xp[j];
                fma2(acc[2 * j + 0], p.x, wv);
                fma2(acc[2 * j + 1], p.y, wv);
            }
        }
    }
    __syncthreads();  // all sx reads done; smem becomes sl

    if (tid < NCLS) {
        #pragma unroll
        for (int j = 0; j < 8; j++) {
            sl[(2 * j + 0) * SLSTRIDE + tid] = lo2(acc[j]);
            sl[(2 * j + 1) * SLSTRIDE + tid] = hi2(acc[j]);
        }
    }
    __syncthreads();

    int wid = tid >> 5, lane = tid & 31;
    for (int s = wid; s < SBT; s += 8) {
        int i = base + s;
        float v[7];
        #pragma unroll
        for (int j = 0; j < 7; j++) v[j] = sl[s * SLSTRIDE + lane + j * 32];
        float m = v[0];
        #pragma unroll
        for (int j = 1; j < 7; j++) m = fmaxf(m, v[j]);
        #pragma unroll
        for (int o = 16; o > 0; o >>= 1) m = fmaxf(m, __shfl_xor_sync(0xffffffffu, m, o));
        float sum = 0.f;
        #pragma unroll
        for (int j = 0; j < 7; j++) sum += __expf(v[j] - m);
        #pragma unroll
        for (int o = 16; o > 0; o >>= 1) sum += __shfl_xor_sync(0xffffffffu, sum, o);
        if (lane == 0) {
            int c = g_class[i];
            g_topprob[i] = __expf(sl[s * SLSTRIDE + c] - m) / sum;
        }
    }
}

// ---------------- bottom: grouped-by-class GEMM + softmax + combine ----------------
__global__ __launch_bounds__(256) void k_bottom(const float* __restrict__ x,
                                                const float* __restrict__ W,
                                                const float* __restrict__ b,
                                                float* __restrict__ out) {
    extern __shared__ float smem[];
    float* sx = smem;
    float* sl = smem;
    __shared__ int sid[SBT];

    int c   = blockIdx.x;
    int n   = g_count[c];
    int off = g_offset[c];
    int tid = threadIdx.x;
    const float* Wc = W + (size_t)c * NHID * NTPC;

    for (int chunk = blockIdx.y; chunk * SBT < n; chunk += gridDim.y) {
        int nv = min(SBT, n - chunk * SBT);
        if (tid < SBT) sid[tid] = (tid < nv) ? g_order[off + chunk * SBT + tid] : 0;
        __syncthreads();

        for (int idx = tid; idx < (NHID / 4) * SBT; idx += 256) {
            int u  = idx / (NHID / 4);
            int k4 = (idx % (NHID / 4)) * 4;
            float4 v = (u < nv) ? *(const float4*)&x[(size_t)sid[u] * NHID + k4]
                                : make_float4(0.f, 0.f, 0.f, 0.f);
            sx[(k4 + 0) * SBT + u] = v.x;
            sx[(k4 + 1) * SBT + u] = v.y;
            sx[(k4 + 2) * SBT + u] = v.z;
            sx[(k4 + 3) * SBT + u] = v.w;
        }
        __syncthreads();

        unsigned long long acc[8];
        if (tid < NTPC) {
            unsigned long long bb = pack2(b[c * NTPC + tid]);
            #pragma unroll
            for (int j = 0; j < 8; j++) acc[j] = bb;
            #pragma unroll 8
            for (int k = 0; k < NHID; k++) {
                unsigned long long wv = pack2(__ldg(&Wc[k * NTPC + tid]));
                const ulonglong2* xp = (const ulonglong2*)(sx + k * SBT);
                #pragma unroll
                for (int j = 0; j < 4; j++) {
                    ulonglong2 p = xp[j];
                    fma2(acc[2 * j + 0], p.x, wv);
                    fma2(acc[2 * j + 1], p.y, wv);
                }
            }
        }
        __syncthreads();

        if (tid < NTPC) {
            #pragma unroll
            for (int j = 0; j < 8; j++) {
                sl[(2 * j + 0) * SLSTRIDE + tid] = lo2(acc[j]);
                sl[(2 * j + 1) * SLSTRIDE + tid] = hi2(acc[j]);
            }
        }
        __syncthreads();

        int wid = tid >> 5, lane = tid & 31;
        for (int s = wid; s < nv; s += 8) {
            int i = sid[s];
            float v[8];
            #pragma unroll
            for (int j = 0; j < 8; j++) {
                int idx = lane + j * 32;
                v[j] = (idx < NTPC) ? sl[s * SLSTRIDE + idx] : -1e30f;
            }
            float m = v[0];
            #pragma unroll
            for (int j = 1; j < 8; j++) m = fmaxf(m, v[j]);
            #pragma unroll
            for (int o = 16; o > 0; o >>= 1) m = fmaxf(m, __shfl_xor_sync(0xffffffffu, m, o));
            float sum = 0.f;
            #pragma unroll
            for (int j = 0; j < 8; j++) {
                int idx = lane + j * 32;
                sum += (idx < NTPC) ? __expf(v[j] - m) : 0.f;
            }
            #pragma unroll
            for (int o = 16; o > 0; o >>= 1) sum += __shfl_xor_sync(0xffffffffu, sum, o);
            if (lane == 0) {
                int tp = g_tok[i];
                float bprob = __expf(sl[s * SLSTRIDE + tp] - m) / sum;
                out[i] = g_topprob[i] * bprob;
            }
        }
        __syncthreads();  // epilogue done before next chunk rewrites sid/sx
    }
}

// ---------------- launch ----------------
extern "C" void kernel_launch(void* const* d_in, const int* in_sizes, int n_in,
                              void* d_out, int out_size) {
    const float* inputs = (const float*)d_in[0];
    const int*   labels = (const int*)d_in[1];
    const float* topW   = (const float*)d_in[2];
    const float* topB   = (const float*)d_in[3];
    const float* botW   = (const float*)d_in[4];
    const float* botB   = (const float*)d_in[5];
    float*       out    = (float*)d_out;

    cudaFuncSetAttribute(k_top,    cudaFuncAttributeMaxDynamicSharedMemorySize, SMEM_BYTES);
    cudaFuncSetAttribute(k_bottom, cudaFuncAttributeMaxDynamicSharedMemorySize, SMEM_BYTES);

    k_prep<<<1, 256>>>(labels);
    k_top<<<BATCH / SBT, 256, SMEM_BYTES>>>(inputs, topW, topB);
    k_bottom<<<dim3(NCLS, 2), 256, SMEM_BYTES>>>(inputs, botW, botB, out);
}

// round 4
// speedup vs baseline: 2.0995x; 1.7046x over previous
#include <cuda_runtime.h>

#define NHID 1024
#define NTPC 225
#define NCLS 224
#define BATCH 2048
#define SBT 16          // samples per tile
#define SLSTRIDE 232    // padded logits row stride (floats)
#define GK 16           // k-group for software pipeline
#define SMEM_BYTES (NHID * SBT * 4)   // 64 KB

// ---------------- scratch ----------------
__device__ int   g_count[NCLS];
__device__ int   g_offset[NCLS];
__device__ int   g_order[BATCH];
__device__ int   g_class[BATCH];
__device__ int   g_tok[BATCH];
__device__ float g_topprob[BATCH];

// ---------------- f32x2 helpers ----------------
__device__ __forceinline__ unsigned long long pack2(float a) {
    unsigned long long r;
    asm("mov.b64 %0, {%1, %1};" : "=l"(r) : "r"(__float_as_uint(a)));
    return r;
}
__device__ __forceinline__ void fma2(unsigned long long& a, unsigned long long x,
                                     unsigned long long w) {
    asm("fma.rn.f32x2 %0, %1, %2, %0;" : "+l"(a) : "l"(x), "l"(w));
}
__device__ __forceinline__ float lo2(unsigned long long a) { return __uint_as_float((unsigned)a); }
__device__ __forceinline__ float hi2(unsigned long long a) { return __uint_as_float((unsigned)(a >> 32)); }

// ---------------- fused preprocessing: count + parallel scan + scatter ----------------
__global__ __launch_bounds__(256) void k_prep(const int* __restrict__ labels) {
    __shared__ int scount[NCLS];
    __shared__ int soff[NCLS];
    __shared__ int sfill[NCLS];
    __shared__ int swsum[8];
    int tid = threadIdx.x;
    int lane = tid & 31, wid = tid >> 5;
    if (tid < NCLS) { scount[tid] = 0; sfill[tid] = 0; }
    __syncthreads();

    for (int i = tid; i < BATCH; i += 256) {
        int l = labels[i];
        int c = l / NTPC;
        c = min(max(c, 0), NCLS - 1);
        g_class[i] = c;
        g_tok[i]   = l - c * NTPC;
        atomicAdd(&scount[c], 1);
    }
    __syncthreads();

    // parallel exclusive scan over 224 counts (7 full warps)
    int incl = 0, own = 0;
    if (tid < NCLS) {
        own = scount[tid];
        incl = own;
        #pragma unroll
        for (int o = 1; o < 32; o <<= 1) {
            int nb = __shfl_up_sync(0xffffffffu, incl, o);
            if (lane >= o) incl += nb;
        }
        if (lane == 31) swsum[wid] = incl;
    }
    __syncthreads();
    if (tid == 0) {
        int acc = 0;
        #pragma unroll
        for (int w = 0; w < 7; w++) { int t = swsum[w]; swsum[w] = acc; acc += t; }
    }
    __syncthreads();
    if (tid < NCLS) {
        int excl = incl - own + swsum[wid];
        soff[tid] = excl;
        g_count[tid]  = own;
        g_offset[tid] = excl;
    }
    __syncthreads();

    for (int i = tid; i < BATCH; i += 256) {
        int c = g_class[i];
        int pos = soff[c] + atomicAdd(&sfill[c], 1);
        g_order[pos] = i;
    }
}

// ---------------- top: [16,1024]x[1024,224] + softmax + select ----------------
__global__ __launch_bounds__(256) void k_top(const float* __restrict__ x,
                                             const float* __restrict__ W,
                                             const float* __restrict__ b) {
    extern __shared__ float smem[];
    float* sx = smem;   // [k][16]
    float* sl = smem;   // overlay after GEMM
    int tid  = threadIdx.x;
    int base = blockIdx.x * SBT;

    for (int idx = tid; idx < (NHID / 4) * SBT; idx += 256) {
        int u  = idx / (NHID / 4);
        int k4 = (idx % (NHID / 4)) * 4;
        float4 v = *(const float4*)&x[(size_t)(base + u) * NHID + k4];
        sx[(k4 + 0) * SBT + u] = v.x;
        sx[(k4 + 1) * SBT + u] = v.y;
        sx[(k4 + 2) * SBT + u] = v.z;
        sx[(k4 + 3) * SBT + u] = v.w;
    }
    __syncthreads();

    unsigned long long acc[8];
    if (tid < NCLS) {
        const float* wp = W + tid;
        unsigned long long bb = pack2(b[tid]);
        #pragma unroll
        for (int j = 0; j < 8; j++) acc[j] = bb;

        float wbuf[GK];
        #pragma unroll
        for (int g = 0; g < GK; g++) wbuf[g] = __ldg(wp + g * NCLS);

        for (int k0 = 0; k0 < NHID; k0 += GK) {
            float wnxt[GK];
            bool more = (k0 + GK < NHID);
            #pragma unroll
            for (int g = 0; g < GK; g++)
                wnxt[g] = more ? __ldg(wp + (k0 + GK + g) * NCLS) : 0.f;
            #pragma unroll
            for (int g = 0; g < GK; g++) {
                unsigned long long wv = pack2(wbuf[g]);
                const ulonglong2* xp = (const ulonglong2*)(sx + (k0 + g) * SBT);
                #pragma unroll
                for (int j = 0; j < 4; j++) {
                    ulonglong2 p = xp[j];
                    fma2(acc[2 * j + 0], p.x, wv);
                    fma2(acc[2 * j + 1], p.y, wv);
                }
            }
            #pragma unroll
            for (int g = 0; g < GK; g++) wbuf[g] = wnxt[g];
        }
    }
    __syncthreads();  // all sx reads done; smem becomes sl

    if (tid < NCLS) {
        #pragma unroll
        for (int j = 0; j < 8; j++) {
            sl[(2 * j + 0) * SLSTRIDE + tid] = lo2(acc[j]);
            sl[(2 * j + 1) * SLSTRIDE + tid] = hi2(acc[j]);
        }
    }
    __syncthreads();

    int wid = tid >> 5, lane = tid & 31;
    for (int s = wid; s < SBT; s += 8) {
        int i = base + s;
        float v[7];
        #pragma unroll
        for (int j = 0; j < 7; j++) v[j] = sl[s * SLSTRIDE + lane + j * 32];
        float m = v[0];
        #pragma unroll
        for (int j = 1; j < 7; j++) m = fmaxf(m, v[j]);
        #pragma unroll
        for (int o = 16; o > 0; o >>= 1) m = fmaxf(m, __shfl_xor_sync(0xffffffffu, m, o));
        float sum = 0.f;
        #pragma unroll
        for (int j = 0; j < 7; j++) sum += __expf(v[j] - m);
        #pragma unroll
        for (int o = 16; o > 0; o >>= 1) sum += __shfl_xor_sync(0xffffffffu, sum, o);
        if (lane == 0) {
            int c = g_class[i];
            g_topprob[i] = __expf(sl[s * SLSTRIDE + c] - m) / sum;
        }
    }
}

// ---------------- bottom: grouped-by-class GEMM + softmax + combine ----------------
__global__ __launch_bounds__(256) void k_bottom(const float* __restrict__ x,
                                                const float* __restrict__ W,
                                                const float* __restrict__ b,
                                                float* __restrict__ out) {
    extern __shared__ float smem[];
    float* sx = smem;
    float* sl = smem;
    __shared__ int sid[SBT];

    int c   = blockIdx.x;
    int n   = g_count[c];
    int off = g_offset[c];
    int tid = threadIdx.x;
    const float* Wc = W + (size_t)c * NHID * NTPC;

    for (int chunk = blockIdx.y; chunk * SBT < n; chunk += gridDim.y) {
        int nv = min(SBT, n - chunk * SBT);
        if (tid < SBT) sid[tid] = (tid < nv) ? g_order[off + chunk * SBT + tid] : 0;
        __syncthreads();

        for (int idx = tid; idx < (NHID / 4) * SBT; idx += 256) {
            int u  = idx / (NHID / 4);
            int k4 = (idx % (NHID / 4)) * 4;
            float4 v = (u < nv) ? *(const float4*)&x[(size_t)sid[u] * NHID + k4]
                                : make_float4(0.f, 0.f, 0.f, 0.f);
            sx[(k4 + 0) * SBT + u] = v.x;
            sx[(k4 + 1) * SBT + u] = v.y;
            sx[(k4 + 2) * SBT + u] = v.z;
            sx[(k4 + 3) * SBT + u] = v.w;
        }
        __syncthreads();

        unsigned long long acc[8];
        if (tid < NTPC) {
            const float* wp = Wc + tid;
            unsigned long long bb = pack2(b[c * NTPC + tid]);
            #pragma unroll
            for (int j = 0; j < 8; j++) acc[j] = bb;

            float wbuf[GK];
            #pragma unroll
            for (int g = 0; g < GK; g++) wbuf[g] = __ldg(wp + g * NTPC);

            for (int k0 = 0; k0 < NHID; k0 += GK) {
                float wnxt[GK];
                bool more = (k0 + GK < NHID);
                #pragma unroll
                for (int g = 0; g < GK; g++)
                    wnxt[g] = more ? __ldg(wp + (k0 + GK + g) * NTPC) : 0.f;
                #pragma unroll
                for (int g = 0; g < GK; g++) {
                    unsigned long long wv = pack2(wbuf[g]);
                    const ulonglong2* xp = (const ulonglong2*)(sx + (k0 + g) * SBT);
                    #pragma unroll
                    for (int j = 0; j < 4; j++) {
                        ulonglong2 p = xp[j];
                        fma2(acc[2 * j + 0], p.x, wv);
                        fma2(acc[2 * j + 1], p.y, wv);
                    }
                }
                #pragma unroll
                for (int g = 0; g < GK; g++) wbuf[g] = wnxt[g];
            }
        }
        __syncthreads();

        if (tid < NTPC) {
            #pragma unroll
            for (int j = 0; j < 8; j++) {
                sl[(2 * j + 0) * SLSTRIDE + tid] = lo2(acc[j]);
                sl[(2 * j + 1) * SLSTRIDE + tid] = hi2(acc[j]);
            }
        }
        __syncthreads();

        int wid = tid >> 5, lane = tid & 31;
        for (int s = wid; s < nv; s += 8) {
            int i = sid[s];
            float v[8];
            #pragma unroll
            for (int j = 0; j < 8; j++) {
                int idx = lane + j * 32;
                v[j] = (idx < NTPC) ? sl[s * SLSTRIDE + idx] : -1e30f;
            }
            float m = v[0];
            #pragma unroll
            for (int j = 1; j < 8; j++) m = fmaxf(m, v[j]);
            #pragma unroll
            for (int o = 16; o > 0; o >>= 1) m = fmaxf(m, __shfl_xor_sync(0xffffffffu, m, o));
            float sum = 0.f;
            #pragma unroll
            for (int j = 0; j < 8; j++) {
                int idx = lane + j * 32;
                sum += (idx < NTPC) ? __expf(v[j] - m) : 0.f;
            }
            #pragma unroll
            for (int o = 16; o > 0; o >>= 1) sum += __shfl_xor_sync(0xffffffffu, sum, o);
            if (lane == 0) {
                int tp = g_tok[i];
                float bprob = __expf(sl[s * SLSTRIDE + tp] - m) / sum;
                out[i] = g_topprob[i] * bprob;
            }
        }
        __syncthreads();  // epilogue done before next chunk rewrites sid/sx
    }
}

// ---------------- launch ----------------
extern "C" void kernel_launch(void* const* d_in, const int* in_sizes, int n_in,
                              void* d_out, int out_size) {
    const float* inputs = (const float*)d_in[0];
    const int*   labels = (const int*)d_in[1];
    const float* topW   = (const float*)d_in[2];
    const float* topB   = (const float*)d_in[3];
    const float* botW   = (const float*)d_in[4];
    const float* botB   = (const float*)d_in[5];
    float*       out    = (float*)d_out;

    cudaFuncSetAttribute(k_top,    cudaFuncAttributeMaxDynamicSharedMemorySize, SMEM_BYTES);
    cudaFuncSetAttribute(k_bottom, cudaFuncAttributeMaxDynamicSharedMemorySize, SMEM_BYTES);

    k_prep<<<1, 256>>>(labels);
    k_top<<<BATCH / SBT, 256, SMEM_BYTES>>>(inputs, topW, topB);
    k_bottom<<<dim3(NCLS, 2), 256, SMEM_BYTES>>>(inputs, botW, botB, out);
}

// round 5
// speedup vs baseline: 2.1725x; 1.0348x over previous
#include <cuda_runtime.h>

#define NHID 1024
#define NTPC 225
#define NCLS 224
#define BATCH 2048
#define SBT 16
#define SLSTRIDE 232
#define GK 16
#define SMEM_BYTES (NHID * SBT * 4)   // 64 KB

// ---------------- scratch ----------------
__device__ int   g_count[NCLS];
__device__ int   g_offset[NCLS];
__device__ int   g_order[BATCH];
__device__ int   g_class[BATCH];
__device__ int   g_tok[BATCH];
__device__ float g_topprob[BATCH];

// ---------------- f32x2 helpers ----------------
__device__ __forceinline__ unsigned long long pack2(float a) {
    unsigned long long r;
    asm("mov.b64 %0, {%1, %1};" : "=l"(r) : "r"(__float_as_uint(a)));
    return r;
}
__device__ __forceinline__ void fma2(unsigned long long& a, unsigned long long x,
                                     unsigned long long w) {
    asm("fma.rn.f32x2 %0, %1, %2, %0;" : "+l"(a) : "l"(x), "l"(w));
}
__device__ __forceinline__ float lo2(unsigned long long a) { return __uint_as_float((unsigned)a); }
__device__ __forceinline__ float hi2(unsigned long long a) { return __uint_as_float((unsigned)(a >> 32)); }

// ---------------- fused preprocessing ----------------
__global__ __launch_bounds__(256) void k_prep(const int* __restrict__ labels) {
    __shared__ int scount[NCLS];
    __shared__ int soff[NCLS];
    __shared__ int sfill[NCLS];
    __shared__ int swsum[8];
    int tid = threadIdx.x;
    int lane = tid & 31, wid = tid >> 5;
    if (tid < NCLS) { scount[tid] = 0; sfill[tid] = 0; }
    __syncthreads();

    for (int i = tid; i < BATCH; i += 256) {
        int l = labels[i];
        int c = l / NTPC;
        c = min(max(c, 0), NCLS - 1);
        g_class[i] = c;
        g_tok[i]   = l - c * NTPC;
        atomicAdd(&scount[c], 1);
    }
    __syncthreads();

    int incl = 0, own = 0;
    if (tid < NCLS) {
        own = scount[tid];
        incl = own;
        #pragma unroll
        for (int o = 1; o < 32; o <<= 1) {
            int nb = __shfl_up_sync(0xffffffffu, incl, o);
            if (lane >= o) incl += nb;
        }
        if (lane == 31) swsum[wid] = incl;
    }
    __syncthreads();
    if (tid == 0) {
        int acc = 0;
        #pragma unroll
        for (int w = 0; w < 7; w++) { int t = swsum[w]; swsum[w] = acc; acc += t; }
    }
    __syncthreads();
    if (tid < NCLS) {
        int excl = incl - own + swsum[wid];
        soff[tid] = excl;
        g_count[tid]  = own;
        g_offset[tid] = excl;
    }
    __syncthreads();

    for (int i = tid; i < BATCH; i += 256) {
        int c = g_class[i];
        int pos = soff[c] + atomicAdd(&sfill[c], 1);
        g_order[pos] = i;
    }
}

// ---------------- shared GEMM core: warpgroup wg computes 8 samples ----------------
// col thread computes acc[4] (f32x2 pairs) for samples [8*wg, 8*wg+8) over k range.
// sx layout [k][16]; sl layout [sample][SLSTRIDE].

// ---------------- top ----------------
__global__ __launch_bounds__(512, 2) void k_top(const float* __restrict__ x,
                                                const float* __restrict__ W,
                                                const float* __restrict__ b) {
    extern __shared__ float smem[];
    float* sx = smem;
    float* sl = smem;
    int tid  = threadIdx.x;
    int base = blockIdx.x * SBT;
    int wg   = tid >> 8;        // 0 or 1
    int col  = tid & 255;

    for (int idx = tid; idx < (NHID / 4) * SBT; idx += 512) {
        int u  = idx / (NHID / 4);
        int k4 = (idx % (NHID / 4)) * 4;
        float4 v = *(const float4*)&x[(size_t)(base + u) * NHID + k4];
        sx[(k4 + 0) * SBT + u] = v.x;
        sx[(k4 + 1) * SBT + u] = v.y;
        sx[(k4 + 2) * SBT + u] = v.z;
        sx[(k4 + 3) * SBT + u] = v.w;
    }
    __syncthreads();

    unsigned long long acc[4];
    if (col < NCLS) {
        const float* wp = W + col;
        unsigned long long bb = pack2(b[col]);
        #pragma unroll
        for (int j = 0; j < 4; j++) acc[j] = bb;

        float wbuf[GK];
        #pragma unroll
        for (int g = 0; g < GK; g++) wbuf[g] = __ldg(wp + g * NCLS);

        for (int k0 = 0; k0 < NHID; k0 += GK) {
            float wnxt[GK];
            bool more = (k0 + GK < NHID);
            #pragma unroll
            for (int g = 0; g < GK; g++)
                wnxt[g] = more ? __ldg(wp + (k0 + GK + g) * NCLS) : 0.f;
            #pragma unroll
            for (int g = 0; g < GK; g++) {
                unsigned long long wv = pack2(wbuf[g]);
                const ulonglong2* xp = (const ulonglong2*)(sx + (k0 + g) * SBT);
                #pragma unroll
                for (int j = 0; j < 2; j++) {
                    ulonglong2 p = xp[wg * 2 + j];
                    fma2(acc[2 * j + 0], p.x, wv);
                    fma2(acc[2 * j + 1], p.y, wv);
                }
            }
            #pragma unroll
            for (int g = 0; g < GK; g++) wbuf[g] = wnxt[g];
        }
    }
    __syncthreads();

    if (col < NCLS) {
        #pragma unroll
        for (int j = 0; j < 2; j++) {
            int s0 = 8 * wg + 4 * j;
            sl[(s0 + 0) * SLSTRIDE + col] = lo2(acc[2 * j + 0]);
            sl[(s0 + 1) * SLSTRIDE + col] = hi2(acc[2 * j + 0]);
            sl[(s0 + 2) * SLSTRIDE + col] = lo2(acc[2 * j + 1]);
            sl[(s0 + 3) * SLSTRIDE + col] = hi2(acc[2 * j + 1]);
        }
    }
    __syncthreads();

    int wid = tid >> 5, lane = tid & 31;   // 16 warps -> 16 samples
    if (wid < SBT) {
        int i = base + wid;
        float v[7];
        #pragma unroll
        for (int j = 0; j < 7; j++) v[j] = sl[wid * SLSTRIDE + lane + j * 32];
        float m = v[0];
        #pragma unroll
        for (int j = 1; j < 7; j++) m = fmaxf(m, v[j]);
        #pragma unroll
        for (int o = 16; o > 0; o >>= 1) m = fmaxf(m, __shfl_xor_sync(0xffffffffu, m, o));
        float sum = 0.f;
        #pragma unroll
        for (int j = 0; j < 7; j++) sum += __expf(v[j] - m);
        #pragma unroll
        for (int o = 16; o > 0; o >>= 1) sum += __shfl_xor_sync(0xffffffffu, sum, o);
        if (lane == 0) {
            int c = g_class[i];
            g_topprob[i] = __expf(sl[wid * SLSTRIDE + c] - m) / sum;
        }
    }
}

// ---------------- bottom ----------------
__global__ __launch_bounds__(512, 2) void k_bottom(const float* __restrict__ x,
                                                   const float* __restrict__ W,
                                                   const float* __restrict__ b,
                                                   float* __restrict__ out) {
    extern __shared__ float smem[];
    float* sx = smem;
    float* sl = smem;
    __shared__ int sid[SBT];

    int c   = blockIdx.x;
    int n   = g_count[c];
    int off = g_offset[c];
    int tid = threadIdx.x;
    int wg  = tid >> 8;
    int col = tid & 255;
    const float* Wc = W + (size_t)c * NHID * NTPC;

    for (int chunk = blockIdx.y; chunk * SBT < n; chunk += gridDim.y) {
        int nv = min(SBT, n - chunk * SBT);
        if (tid < SBT) sid[tid] = (tid < nv) ? g_order[off + chunk * SBT + tid] : 0;
        __syncthreads();

        for (int idx = tid; idx < (NHID / 4) * SBT; idx += 512) {
            int u  = idx / (NHID / 4);
            int k4 = (idx % (NHID / 4)) * 4;
            float4 v = (u < nv) ? *(const float4*)&x[(size_t)sid[u] * NHID + k4]
                                : make_float4(0.f, 0.f, 0.f, 0.f);
            sx[(k4 + 0) * SBT + u] = v.x;
            sx[(k4 + 1) * SBT + u] = v.y;
            sx[(k4 + 2) * SBT + u] = v.z;
            sx[(k4 + 3) * SBT + u] = v.w;
        }
        __syncthreads();

        unsigned long long acc[4];
        if (col < NTPC) {
            const float* wp = Wc + col;
            unsigned long long bb = pack2(b[c * NTPC + col]);
            #pragma unroll
            for (int j = 0; j < 4; j++) acc[j] = bb;

            float wbuf[GK];
            #pragma unroll
            for (int g = 0; g < GK; g++) wbuf[g] = __ldg(wp + g * NTPC);

            for (int k0 = 0; k0 < NHID; k0 += GK) {
                float wnxt[GK];
                bool more = (k0 + GK < NHID);
                #pragma unroll
                for (int g = 0; g < GK; g++)
                    wnxt[g] = more ? __ldg(wp + (k0 + GK + g) * NTPC) : 0.f;
                #pragma unroll
                for (int g = 0; g < GK; g++) {
                    unsigned long long wv = pack2(wbuf[g]);
                    const ulonglong2* xp = (const ulonglong2*)(sx + (k0 + g) * SBT);
                    #pragma unroll
                    for (int j = 0; j < 2; j++) {
                        ulonglong2 p = xp[wg * 2 + j];
                        fma2(acc[2 * j + 0], p.x, wv);
                        fma2(acc[2 * j + 1], p.y, wv);
                    }
                }
                #pragma unroll
                for (int g = 0; g < GK; g++) wbuf[g] = wnxt[g];
            }
        }
        __syncthreads();

        if (col < NTPC) {
            #pragma unroll
            for (int j = 0; j < 2; j++) {
                int s0 = 8 * wg + 4 * j;
                sl[(s0 + 0) * SLSTRIDE + col] = lo2(acc[2 * j + 0]);
                sl[(s0 + 1) * SLSTRIDE + col] = hi2(acc[2 * j + 0]);
                sl[(s0 + 2) * SLSTRIDE + col] = lo2(acc[2 * j + 1]);
                sl[(s0 + 3) * SLSTRIDE + col] = hi2(acc[2 * j + 1]);
            }
        }
        __syncthreads();

        int wid = tid >> 5, lane = tid & 31;
        if (wid < nv) {
            int i = sid[wid];
            float v[8];
            #pragma unroll
            for (int j = 0; j < 8; j++) {
                int idx = lane + j * 32;
                v[j] = (idx < NTPC) ? sl[wid * SLSTRIDE + idx] : -1e30f;
            }
            float m = v[0];
            #pragma unroll
            for (int j = 1; j < 8; j++) m = fmaxf(m, v[j]);
            #pragma unroll
            for (int o = 16; o > 0; o >>= 1) m = fmaxf(m, __shfl_xor_sync(0xffffffffu, m, o));
            float sum = 0.f;
            #pragma unroll
            for (int j = 0; j < 8; j++) {
                int idx = lane + j * 32;
                sum += (idx < NTPC) ? __expf(v[j] - m) : 0.f;
            }
            #pragma unroll
            for (int o = 16; o > 0; o >>= 1) sum += __shfl_xor_sync(0xffffffffu, sum, o);
            if (lane == 0) {
                int tp = g_tok[i];
                float bprob = __expf(sl[wid * SLSTRIDE + tp] - m) / sum;
                out[i] = g_topprob[i] * bprob;
            }
        }
        __syncthreads();
    }
}

// ---------------- launch ----------------
extern "C" void kernel_launch(void* const* d_in, const int* in_sizes, int n_in,
                              void* d_out, int out_size) {
    const float* inputs = (const float*)d_in[0];
    const int*   labels = (const int*)d_in[1];
    const float* topW   = (const float*)d_in[2];
    const float* topB   = (const float*)d_in[3];
    const float* botW   = (const float*)d_in[4];
    const float* botB   = (const float*)d_in[5];
    float*       out    = (float*)d_out;

    cudaFuncSetAttribute(k_top,    cudaFuncAttributeMaxDynamicSharedMemorySize, SMEM_BYTES);
    cudaFuncSetAttribute(k_bottom, cudaFuncAttributeMaxDynamicSharedMemorySize, SMEM_BYTES);

    k_prep<<<1, 256>>>(labels);
    k_top<<<BATCH / SBT, 512, SMEM_BYTES>>>(inputs, topW, topB);
    k_bottom<<<dim3(NCLS, 2), 512, SMEM_BYTES>>>(inputs, botW, botB, out);
}